// round 10
// baseline (speedup 1.0000x reference)
#include <cuda_runtime.h>
#include <cuda_fp16.h>
#include <cstdint>

// Problem constants (static per reference)
#define BB    8
#define NNODE 384
#define FF    64
#define TT    192
#define NSRC  383         // T + TAU - 1
#define NROWS (5*BB*TT)   // S*B*192 = 7680 argmax rows

// ---------------- device scratch (no allocs allowed) ----------------
__device__ float g_P[BB*NNODE*FF];          // nodes @ w1_top + b1
__device__ float g_Q[BB*NNODE*FF];          // nodes @ w1_bot
__device__ float g_logits[BB*TT*NSRC];      // per-edge logits
__device__ __half g_w2split[2*64*64];       // [plane][j][k] = split_p(w2[k][j])

// ---------------- helpers ----------------
// exact 2-way fp16 split of fp32: v = h + m + r, |r| <= 2^-24 |v|
__device__ __forceinline__ void split2(float v, __half& h, __half& m) {
    h = __float2half_rn(v);
    float r1 = v - __half2float(h);        // exact
    m = __float2half_rn(r1);
}
__device__ __forceinline__ uint32_t pack_h2(__half a, __half b) {
    __half2 t = __halves2half2(a, b);      // a = low half (even k)
    return *reinterpret_cast<uint32_t*>(&t);
}
__device__ __forceinline__ uint32_t smem_u32(const void* p) {
    return (uint32_t)__cvta_generic_to_shared(p);
}
// m16n8k16 row.col f32.f16.f16.f32 (plain sm_80+ PTX; HMMA on sm_103a)
__device__ __forceinline__ void mma16816(float* c, const uint32_t* a,
                                         uint32_t b0, uint32_t b1) {
    asm volatile(
        "mma.sync.aligned.m16n8k16.row.col.f32.f16.f16.f32 "
        "{%0,%1,%2,%3}, {%4,%5,%6,%7}, {%8,%9}, {%0,%1,%2,%3};"
        : "+f"(c[0]), "+f"(c[1]), "+f"(c[2]), "+f"(c[3])
        : "r"(a[0]), "r"(a[1]), "r"(a[2]), "r"(a[3]), "r"(b0), "r"(b1));
}
__device__ __forceinline__ void ldsm_x4(uint32_t* r, uint32_t addr) {
    asm volatile("ldmatrix.sync.aligned.m8n8.x4.shared.b16 {%0,%1,%2,%3}, [%4];"
                 : "=r"(r[0]), "=r"(r[1]), "=r"(r[2]), "=r"(r[3]) : "r"(addr));
}

// ---------------- K1: factor layer 1 per-node (+ fused w2 split) ----------
// 384 blocks x 8 rows; one sync; 4 independent FMA chains per thread.
__global__ void k_precompute(const float* __restrict__ nodes,
                             const float* __restrict__ w1,
                             const float* __restrict__ b1,
                             const float* __restrict__ w2)
{
    __shared__ float w1s[128*64];
    __shared__ float nds[8][64];
    int tid = threadIdx.x;

    // fused: blocks 0..15 also pre-split w2^T into 2 fp16 planes
    if (blockIdx.x < 16) {
        int idx = blockIdx.x * 256 + tid;       // 4096 = [j][k]
        int j = idx >> 6, k = idx & 63;
        float v = w2[k*64 + j];
        __half h, m;
        split2(v, h, m);
        g_w2split[idx]        = h;
        g_w2split[4096 + idx] = m;
    }

    int row0 = blockIdx.x * 8;                  // 384 blocks * 8 rows = 3072
    // stage w1 (2048 float4) + 8 node rows (128 float4)
    {
        const float4* src = (const float4*)w1;
        float4* dst = (float4*)w1s;
        #pragma unroll
        for (int t = 0; t < 8; t++) dst[tid + 256*t] = src[tid + 256*t];
        if (tid < 128)
            ((float4*)nds)[tid] = ((const float4*)(nodes + row0*64))[tid];
    }
    __syncthreads();

    int f = tid & 63, rs = tid >> 6;            // rs 0..3
    float b1v = b1[f];
    float pA = b1v, qA = 0.f, pB = b1v, qB = 0.f;
    #pragma unroll
    for (int k = 0; k < 64; k++) {
        float w1t = w1s[k*64 + f];
        float w1b = w1s[(64+k)*64 + f];
        float nA = nds[rs][k];
        float nB = nds[rs + 4][k];
        pA = fmaf(nA, w1t, pA);
        qA = fmaf(nA, w1b, qA);
        pB = fmaf(nB, w1t, pB);
        qB = fmaf(nB, w1b, qB);
    }
    int rowA = row0 + rs, rowB = row0 + rs + 4;
    g_P[rowA*64 + f] = pA;
    g_Q[rowA*64 + f] = qA;
    g_P[rowB*64 + f] = pB;
    g_Q[rowB*64 + f] = qB;
}

// ---------------- K2: fused edge MLP via mma.sync fp16x2 + LDSM ----------
// 128 threads, 128 edges/block, single __syncthreads. Params read straight
// from gmem (L1 broadcast). Also zeroes its slice of the output grid.
#define A_BASE   0
#define B_BASE   (2*16384)                   // 32768
#define SMEM_BYTES (B_BASE + 2*8192)         // 49152
__global__ void __launch_bounds__(128, 4) k_edges(
    const float* __restrict__ b2, const float* __restrict__ g2,
    const float* __restrict__ be2, const float* __restrict__ w3,
    const float* __restrict__ b3, const float* __restrict__ g1,
    const float* __restrict__ be1, float4* __restrict__ out4)
{
    extern __shared__ __align__(128) char smem[];

    int i = blockIdx.y, b = blockIdx.z;
    int tid  = threadIdx.x;

    // ---- fused output zeroing: 4608 blocks x 64 float4 = full grid ----
    {
        int bid = blockIdx.x + 3*(blockIdx.y + TT*blockIdx.z);   // 0..4607
        if (tid < 64)
            out4[bid*64 + tid] = make_float4(0.f, 0.f, 0.f, 0.f);
    }

    int sink = 192 + i;
    int L = sink;
    int c_base = blockIdx.x * 128;
    if (c_base >= L) return;                 // uniform early exit (before sync)

    int lane = tid & 31;
    int w    = tid >> 5;

    // stage B planes (pre-split fp16 w2^T), swizzled: 1024 uint4 (no sync yet)
    {
        const uint4* src = (const uint4*)g_w2split;
        for (int idx = tid; idx < 1024; idx += 128) {
            int p = idx >> 9, q = idx & 511;
            int j = q >> 3, u = q & 7;
            *(uint4*)(smem + B_BASE + p*8192 + j*128 + ((u ^ (j & 7)) << 4)) = src[idx];
        }
    }

    // ---- phase 1: thread-per-edge LN1 + fp16 split -> A planes ----
    {
        int e = tid;
        int c = c_base + e;                  // < 384: safe read
        const float4* qrow = (const float4*)&g_Q[((b*NNODE) + c)*64];
        const float4* prow = (const float4*)&g_P[((b*NNODE) + sink)*64];
        float4 x[16];
        float s = 0.f;
        #pragma unroll
        for (int u = 0; u < 16; u++) {
            float4 q = __ldg(&qrow[u]);
            float4 p = __ldg(&prow[u]);      // broadcast address -> L1 hit
            x[u].x = fmaxf(p.x + q.x, 0.f);
            x[u].y = fmaxf(p.y + q.y, 0.f);
            x[u].z = fmaxf(p.z + q.z, 0.f);
            x[u].w = fmaxf(p.w + q.w, 0.f);
            s += x[u].x + x[u].y + x[u].z + x[u].w;
        }
        float mu = s * (1.f/64.f);
        float vs = 0.f;
        #pragma unroll
        for (int u = 0; u < 16; u++) {
            float d0 = x[u].x - mu, d1 = x[u].y - mu;
            float d2 = x[u].z - mu, d3 = x[u].w - mu;
            vs += d0*d0 + d1*d1 + d2*d2 + d3*d3;
        }
        float rstd = 1.f / sqrtf(vs * (1.f/64.f) + 1e-5f);
        #pragma unroll
        for (int u = 0; u < 16; u++) {
            float4 gv = __ldg((const float4*)&g1[u*4]);
            float4 bv = __ldg((const float4*)&be1[u*4]);
            x[u].x = fmaf((x[u].x - mu)*rstd, gv.x, bv.x);
            x[u].y = fmaf((x[u].y - mu)*rstd, gv.y, bv.y);
            x[u].z = fmaf((x[u].z - mu)*rstd, gv.z, bv.z);
            x[u].w = fmaf((x[u].w - mu)*rstd, gv.w, bv.w);
        }
        int rowoff = e * 128;
        #pragma unroll
        for (int u2 = 0; u2 < 8; u2++) {
            float4 a0 = x[2*u2], a1 = x[2*u2 + 1];
            float vv[8] = {a0.x, a0.y, a0.z, a0.w, a1.x, a1.y, a1.z, a1.w};
            __half h[8], m[8];
            #pragma unroll
            for (int t = 0; t < 8; t++) split2(vv[t], h[t], m[t]);
            uint4 uh = make_uint4(pack_h2(h[0],h[1]), pack_h2(h[2],h[3]),
                                  pack_h2(h[4],h[5]), pack_h2(h[6],h[7]));
            uint4 um = make_uint4(pack_h2(m[0],m[1]), pack_h2(m[2],m[3]),
                                  pack_h2(m[4],m[5]), pack_h2(m[6],m[7]));
            int phys = rowoff + ((u2 ^ (e & 7)) << 4);
            *(uint4*)(smem + A_BASE         + phys) = uh;
            *(uint4*)(smem + A_BASE + 16384 + phys) = um;
        }
    }
    __syncthreads();    // covers A-plane writes AND B staging

    // ---- phase 2: HMMA GEMM, 3 products, LDSM fragment loads ----
    int e0 = w * 32;
    int q  = lane >> 2;          // fragment row group
    int kq = (lane & 3) * 2;     // fragment col pair

    float acc[2][8][4];
    #pragma unroll
    for (int mt = 0; mt < 2; mt++)
        #pragma unroll
        for (int nt = 0; nt < 8; nt++)
            #pragma unroll
            for (int t = 0; t < 4; t++) acc[mt][nt][t] = 0.f;

    uint32_t Ah32 = smem_u32(smem + A_BASE);
    uint32_t Am32 = Ah32 + 16384;
    uint32_t Bh32 = smem_u32(smem + B_BASE);
    uint32_t Bm32 = Bh32 + 8192;

    // per-lane ldmatrix row addressing
    int sub = lane >> 3, l8 = lane & 7;
    int rA[2], rA7[2];
    #pragma unroll
    for (int mt = 0; mt < 2; mt++) {
        int r = e0 + mt*16 + ((sub & 1) << 3) + l8;
        rA[mt] = r * 128;
        rA7[mt] = r & 7;
    }
    int kbitA = sub >> 1;
    int rB[4], rB7[4];
    #pragma unroll
    for (int p = 0; p < 4; p++) {
        int j = p*16 + ((sub >> 1) << 3) + l8;
        rB[p] = j * 128;
        rB7[p] = j & 7;
    }
    int kbitB = sub & 1;

    #pragma unroll
    for (int ks = 0; ks < 4; ks++) {
        uint32_t ah[2][4], am[2][4];
        #pragma unroll
        for (int mt = 0; mt < 2; mt++) {
            uint32_t off = rA[mt] + (((2*ks + kbitA) ^ rA7[mt]) << 4);
            ldsm_x4(ah[mt], Ah32 + off);
            ldsm_x4(am[mt], Am32 + off);
        }
        uint32_t bh[8][2], bm[8][2];
        #pragma unroll
        for (int p = 0; p < 4; p++) {
            uint32_t off = rB[p] + (((2*ks + kbitB) ^ rB7[p]) << 4);
            uint32_t t4[4];
            ldsm_x4(t4, Bh32 + off);
            bh[2*p][0] = t4[0]; bh[2*p][1] = t4[1];
            bh[2*p+1][0] = t4[2]; bh[2*p+1][1] = t4[3];
            ldsm_x4(t4, Bm32 + off);
            bm[2*p][0] = t4[0]; bm[2*p][1] = t4[1];
            bm[2*p+1][0] = t4[2]; bm[2*p+1][1] = t4[3];
        }
        #pragma unroll
        for (int nt = 0; nt < 8; nt++) {
            mma16816(acc[0][nt], ah[0], bh[nt][0], bh[nt][1]);   // h*h
            mma16816(acc[1][nt], ah[1], bh[nt][0], bh[nt][1]);
            mma16816(acc[0][nt], ah[0], bm[nt][0], bm[nt][1]);   // h*m
            mma16816(acc[1][nt], ah[1], bm[nt][0], bm[nt][1]);
            mma16816(acc[0][nt], am[0], bh[nt][0], bh[nt][1]);   // m*h
            mma16816(acc[1][nt], am[1], bh[nt][0], bh[nt][1]);
        }
    }

    // ---- epilogue: relu + LN2 via quad reductions -> logits ----
    {
        float2 pb2[8], pg2[8], pbe2[8], pw3[8];
        #pragma unroll
        for (int nt = 0; nt < 8; nt++) {
            int jc = nt*8 + kq;
            pb2[nt]  = __ldg((const float2*)&b2[jc]);
            pg2[nt]  = __ldg((const float2*)&g2[jc]);
            pbe2[nt] = __ldg((const float2*)&be2[jc]);
            pw3[nt]  = __ldg((const float2*)&w3[jc]);
        }
        float b3v = __ldg(&b3[0]);
        float* lrow = g_logits + (b*TT + i)*NSRC;

        #pragma unroll
        for (int mt = 0; mt < 2; mt++) {
            float xA[16], xB[16];
            float sA = 0.f, sB = 0.f;
            #pragma unroll
            for (int nt = 0; nt < 8; nt++) {
                xA[2*nt]   = fmaxf(acc[mt][nt][0] + pb2[nt].x, 0.f);
                xA[2*nt+1] = fmaxf(acc[mt][nt][1] + pb2[nt].y, 0.f);
                xB[2*nt]   = fmaxf(acc[mt][nt][2] + pb2[nt].x, 0.f);
                xB[2*nt+1] = fmaxf(acc[mt][nt][3] + pb2[nt].y, 0.f);
                sA += xA[2*nt] + xA[2*nt+1];
                sB += xB[2*nt] + xB[2*nt+1];
            }
            sA += __shfl_xor_sync(0xffffffffu, sA, 1);
            sA += __shfl_xor_sync(0xffffffffu, sA, 2);
            sB += __shfl_xor_sync(0xffffffffu, sB, 1);
            sB += __shfl_xor_sync(0xffffffffu, sB, 2);
            float muA = sA * (1.f/64.f), muB = sB * (1.f/64.f);
            float vA = 0.f, vB = 0.f;
            #pragma unroll
            for (int t = 0; t < 16; t++) {
                float dA = xA[t] - muA; vA += dA*dA;
                float dB = xB[t] - muB; vB += dB*dB;
            }
            vA += __shfl_xor_sync(0xffffffffu, vA, 1);
            vA += __shfl_xor_sync(0xffffffffu, vA, 2);
            vB += __shfl_xor_sync(0xffffffffu, vB, 1);
            vB += __shfl_xor_sync(0xffffffffu, vB, 2);
            float rsA = 1.f / sqrtf(vA * (1.f/64.f) + 1e-5f);
            float rsB = 1.f / sqrtf(vB * (1.f/64.f) + 1e-5f);
            float dA = 0.f, dB = 0.f;
            #pragma unroll
            for (int nt = 0; nt < 8; nt++) {
                dA = fmaf(fmaf((xA[2*nt]   - muA)*rsA, pg2[nt].x, pbe2[nt].x), pw3[nt].x, dA);
                dA = fmaf(fmaf((xA[2*nt+1] - muA)*rsA, pg2[nt].y, pbe2[nt].y), pw3[nt].y, dA);
                dB = fmaf(fmaf((xB[2*nt]   - muB)*rsB, pg2[nt].x, pbe2[nt].x), pw3[nt].x, dB);
                dB = fmaf(fmaf((xB[2*nt+1] - muB)*rsB, pg2[nt].y, pbe2[nt].y), pw3[nt].y, dB);
            }
            dA += __shfl_xor_sync(0xffffffffu, dA, 1);
            dA += __shfl_xor_sync(0xffffffffu, dA, 2);
            dB += __shfl_xor_sync(0xffffffffu, dB, 1);
            dB += __shfl_xor_sync(0xffffffffu, dB, 2);
            if ((lane & 3) == 0) {
                int eA = e0 + mt*16 + q;
                int cA = c_base + eA;
                if (cA < L) lrow[cA] = dA + b3v;
                int cB = cA + 8;
                if (cB < L) lrow[cB] = dB + b3v;
            }
        }
    }
}

// ---------------- K4: gumbel argmax + scatter 1.0 ----------------
__global__ void k_argmax(const float* __restrict__ gumbel, float* __restrict__ out)
{
    int row = blockIdx.x * 8 + (threadIdx.x >> 5);
    if (row >= NROWS) return;
    int lane = threadIdx.x & 31;
    int i  = row % TT;
    int sb = row / TT;
    int b  = sb & 7;
    int L  = 192 + i;

    const float* lg = g_logits + (size_t)((b*TT + i)) * NSRC;
    const float* gb = gumbel   + (size_t)row * NSRC;

    float best = -__int_as_float(0x7f800000);
    int bidx = 0;
    int c = lane;
    for (; c + 96 < L; c += 128) {           // 4-way unroll for MLP
        float v0 = __ldg(&lg[c])      + __ldg(&gb[c]);
        float v1 = __ldg(&lg[c + 32]) + __ldg(&gb[c + 32]);
        float v2 = __ldg(&lg[c + 64]) + __ldg(&gb[c + 64]);
        float v3 = __ldg(&lg[c + 96]) + __ldg(&gb[c + 96]);
        if (v0 > best) { best = v0; bidx = c; }
        if (v1 > best) { best = v1; bidx = c + 32; }
        if (v2 > best) { best = v2; bidx = c + 64; }
        if (v3 > best) { best = v3; bidx = c + 96; }
    }
    for (; c < L; c += 32) {
        float v = __ldg(&lg[c]) + __ldg(&gb[c]);
        if (v > best) { best = v; bidx = c; }
    }
    #pragma unroll
    for (int o = 16; o; o >>= 1) {
        float ov = __shfl_xor_sync(0xffffffffu, best, o);
        int   oi = __shfl_xor_sync(0xffffffffu, bidx, o);
        if (ov > best || (ov == best && oi < bidx)) { best = ov; bidx = oi; }
    }
    if (lane == 0)
        out[((size_t)(b*NNODE) + 192 + i) * NNODE + bidx] = 1.0f;
}

// ---------------- launch ----------------
extern "C" void kernel_launch(void* const* d_in, const int* in_sizes, int n_in,
                              void* d_out, int out_size)
{
    const float* nodes = (const float*)d_in[0];
    const float* w1    = (const float*)d_in[1];
    const float* b1    = (const float*)d_in[2];
    const float* g1    = (const float*)d_in[3];
    const float* be1   = (const float*)d_in[4];
    const float* w2    = (const float*)d_in[5];
    const float* b2    = (const float*)d_in[6];
    const float* g2    = (const float*)d_in[7];
    const float* be2   = (const float*)d_in[8];
    const float* w3    = (const float*)d_in[9];
    const float* b3    = (const float*)d_in[10];
    const float* gum   = (const float*)d_in[11];
    float* out = (float*)d_out;

    cudaFuncSetAttribute(k_edges, cudaFuncAttributeMaxDynamicSharedMemorySize,
                         SMEM_BYTES);

    k_precompute<<<384, 256>>>(nodes, w1, b1, w2);
    k_edges<<<dim3(3, TT, BB), 128, SMEM_BYTES>>>(b2, g2, be2, w3, b3, g1, be1,
                                                  (float4*)out);
    k_argmax<<<NROWS / 8, 256>>>(gum, out);
}

// round 11
// speedup vs baseline: 1.1155x; 1.1155x over previous
#include <cuda_runtime.h>
#include <cuda_fp16.h>
#include <cstdint>

// Problem constants (static per reference)
#define BB    8
#define NNODE 384
#define FF    64
#define TT    192
#define NSRC  383         // T + TAU - 1
#define NROWS (5*BB*TT)   // S*B*192 = 7680 argmax rows

// ---------------- device scratch (no allocs allowed) ----------------
__device__ float g_P[BB*NNODE*FF];          // nodes @ w1_top + b1
__device__ float g_Q[BB*NNODE*FF];          // nodes @ w1_bot
__device__ float g_logits[BB*TT*NSRC];      // per-edge logits
__device__ __half g_w2split[2*64*64];       // [plane][j][k] = split_p(w2[k][j])

// ---------------- helpers ----------------
// exact 2-way fp16 split of fp32: v = h + m + r, |r| <= 2^-24 |v|
__device__ __forceinline__ void split2(float v, __half& h, __half& m) {
    h = __float2half_rn(v);
    float r1 = v - __half2float(h);        // exact
    m = __float2half_rn(r1);
}
__device__ __forceinline__ uint32_t pack_h2(__half a, __half b) {
    __half2 t = __halves2half2(a, b);      // a = low half (even k)
    return *reinterpret_cast<uint32_t*>(&t);
}
__device__ __forceinline__ uint32_t smem_u32(const void* p) {
    return (uint32_t)__cvta_generic_to_shared(p);
}
// m16n8k16 row.col f32.f16.f16.f32 (plain sm_80+ PTX; HMMA on sm_103a)
__device__ __forceinline__ void mma16816(float* c, const uint32_t* a,
                                         uint32_t b0, uint32_t b1) {
    asm volatile(
        "mma.sync.aligned.m16n8k16.row.col.f32.f16.f16.f32 "
        "{%0,%1,%2,%3}, {%4,%5,%6,%7}, {%8,%9}, {%0,%1,%2,%3};"
        : "+f"(c[0]), "+f"(c[1]), "+f"(c[2]), "+f"(c[3])
        : "r"(a[0]), "r"(a[1]), "r"(a[2]), "r"(a[3]), "r"(b0), "r"(b1));
}
__device__ __forceinline__ void ldsm_x4(uint32_t* r, uint32_t addr) {
    asm volatile("ldmatrix.sync.aligned.m8n8.x4.shared.b16 {%0,%1,%2,%3}, [%4];"
                 : "=r"(r[0]), "=r"(r[1]), "=r"(r[2]), "=r"(r[3]) : "r"(addr));
}

// ---------------- K1: factor layer 1 per-node (+ fused w2 split) ----------
// 384 blocks x 8 rows; one sync; 4 independent FMA chains per thread.
// (R10-profiled: 7.5us, kept.)
__global__ void k_precompute(const float* __restrict__ nodes,
                             const float* __restrict__ w1,
                             const float* __restrict__ b1,
                             const float* __restrict__ w2)
{
    __shared__ float w1s[128*64];
    __shared__ float nds[8][64];
    int tid = threadIdx.x;

    // fused: blocks 0..15 also pre-split w2^T into 2 fp16 planes
    if (blockIdx.x < 16) {
        int idx = blockIdx.x * 256 + tid;       // 4096 = [j][k]
        int j = idx >> 6, k = idx & 63;
        float v = w2[k*64 + j];
        __half h, m;
        split2(v, h, m);
        g_w2split[idx]        = h;
        g_w2split[4096 + idx] = m;
    }

    int row0 = blockIdx.x * 8;                  // 384 blocks * 8 rows = 3072
    // stage w1 (2048 float4) + 8 node rows (128 float4)
    {
        const float4* src = (const float4*)w1;
        float4* dst = (float4*)w1s;
        #pragma unroll
        for (int t = 0; t < 8; t++) dst[tid + 256*t] = src[tid + 256*t];
        if (tid < 128)
            ((float4*)nds)[tid] = ((const float4*)(nodes + row0*64))[tid];
    }
    __syncthreads();

    int f = tid & 63, rs = tid >> 6;            // rs 0..3
    float b1v = b1[f];
    float pA = b1v, qA = 0.f, pB = b1v, qB = 0.f;
    #pragma unroll
    for (int k = 0; k < 64; k++) {
        float w1t = w1s[k*64 + f];
        float w1b = w1s[(64+k)*64 + f];
        float nA = nds[rs][k];
        float nB = nds[rs + 4][k];
        pA = fmaf(nA, w1t, pA);
        qA = fmaf(nA, w1b, qA);
        pB = fmaf(nB, w1t, pB);
        qB = fmaf(nB, w1b, qB);
    }
    int rowA = row0 + rs, rowB = row0 + rs + 4;
    g_P[rowA*64 + f] = pA;
    g_Q[rowA*64 + f] = qA;
    g_P[rowB*64 + f] = pB;
    g_Q[rowB*64 + f] = qB;
}

// ---------------- K2: fused edge MLP via mma.sync fp16x2 + LDSM ----------
// EXACT Round-9 (94.3us) version: smem param staging, occ 3, two syncs.
// 128 threads, 128 edges/block. Also zeroes its slice of the output grid.
#define A_BASE   2048
#define B_BASE   (A_BASE + 2*16384)          // 34816
#define SMEM_BYTES (B_BASE + 2*8192)         // 51200
__global__ void __launch_bounds__(128, 3) k_edges(
    const float* __restrict__ b2, const float* __restrict__ g2,
    const float* __restrict__ be2, const float* __restrict__ w3,
    const float* __restrict__ b3, const float* __restrict__ g1,
    const float* __restrict__ be1, float4* __restrict__ out4)
{
    extern __shared__ __align__(128) char smem[];
    float* smf    = (float*)smem;
    float* sp_p   = smf;                     // 7x64 param block (1792B < 2048)
    float* sp_g1  = sp_p  + 64;
    float* sp_be1 = sp_g1 + 64;
    float* sp_b2  = sp_be1+ 64;
    float* sp_g2  = sp_b2 + 64;
    float* sp_be2 = sp_g2 + 64;
    float* sp_w3  = sp_be2+ 64;

    int i = blockIdx.y, b = blockIdx.z;
    int tid  = threadIdx.x;

    // ---- fused output zeroing: 4608 blocks x 64 float4 = full grid ----
    {
        int bid = blockIdx.x + 3*(blockIdx.y + TT*blockIdx.z);   // 0..4607
        if (tid < 64)
            out4[bid*64 + tid] = make_float4(0.f, 0.f, 0.f, 0.f);
    }

    int sink = 192 + i;
    int L = sink;
    int c_base = blockIdx.x * 128;
    if (c_base >= L) return;                 // uniform early exit (before syncs)

    int lane = tid & 31;
    int w    = tid >> 5;

    // stage B planes (pre-split fp16 w2^T), swizzled: 1024 uint4
    {
        const uint4* src = (const uint4*)g_w2split;
        for (int idx = tid; idx < 1024; idx += 128) {
            int p = idx >> 9, q = idx & 511;
            int j = q >> 3, u = q & 7;
            *(uint4*)(smem + B_BASE + p*8192 + j*128 + ((u ^ (j & 7)) << 4)) = src[idx];
        }
    }
    if (tid < 64) {
        sp_p[tid]  = g_P[(b*NNODE + sink)*64 + tid];
        sp_g1[tid] = g1[tid];
        sp_be1[tid]= be1[tid];
        sp_b2[tid] = b2[tid];
        sp_g2[tid] = g2[tid];
        sp_be2[tid]= be2[tid];
        sp_w3[tid] = w3[tid];
    }
    __syncthreads();

    // ---- phase 1: thread-per-edge LN1 + fp16 split -> A planes ----
    {
        int e = tid;
        int c = c_base + e;                  // < 384: safe read
        const float4* qrow = (const float4*)&g_Q[((b*NNODE) + c)*64];
        float4 x[16];
        float s = 0.f;
        #pragma unroll
        for (int u = 0; u < 16; u++) {
            float4 q = __ldg(&qrow[u]);
            float4 p = *(const float4*)&sp_p[u*4];
            x[u].x = fmaxf(p.x + q.x, 0.f);
            x[u].y = fmaxf(p.y + q.y, 0.f);
            x[u].z = fmaxf(p.z + q.z, 0.f);
            x[u].w = fmaxf(p.w + q.w, 0.f);
            s += x[u].x + x[u].y + x[u].z + x[u].w;
        }
        float mu = s * (1.f/64.f);
        float vs = 0.f;
        #pragma unroll
        for (int u = 0; u < 16; u++) {
            float d0 = x[u].x - mu, d1 = x[u].y - mu;
            float d2 = x[u].z - mu, d3 = x[u].w - mu;
            vs += d0*d0 + d1*d1 + d2*d2 + d3*d3;
        }
        float rstd = 1.f / sqrtf(vs * (1.f/64.f) + 1e-5f);
        #pragma unroll
        for (int u = 0; u < 16; u++) {
            float4 gv = *(const float4*)&sp_g1[u*4];
            float4 bv = *(const float4*)&sp_be1[u*4];
            x[u].x = fmaf((x[u].x - mu)*rstd, gv.x, bv.x);
            x[u].y = fmaf((x[u].y - mu)*rstd, gv.y, bv.y);
            x[u].z = fmaf((x[u].z - mu)*rstd, gv.z, bv.z);
            x[u].w = fmaf((x[u].w - mu)*rstd, gv.w, bv.w);
        }
        int rowoff = e * 128;
        #pragma unroll
        for (int u2 = 0; u2 < 8; u2++) {
            float4 a0 = x[2*u2], a1 = x[2*u2 + 1];
            float vv[8] = {a0.x, a0.y, a0.z, a0.w, a1.x, a1.y, a1.z, a1.w};
            __half h[8], m[8];
            #pragma unroll
            for (int t = 0; t < 8; t++) split2(vv[t], h[t], m[t]);
            uint4 uh = make_uint4(pack_h2(h[0],h[1]), pack_h2(h[2],h[3]),
                                  pack_h2(h[4],h[5]), pack_h2(h[6],h[7]));
            uint4 um = make_uint4(pack_h2(m[0],m[1]), pack_h2(m[2],m[3]),
                                  pack_h2(m[4],m[5]), pack_h2(m[6],m[7]));
            int phys = rowoff + ((u2 ^ (e & 7)) << 4);
            *(uint4*)(smem + A_BASE         + phys) = uh;
            *(uint4*)(smem + A_BASE + 16384 + phys) = um;
        }
    }
    __syncthreads();

    // ---- phase 2: HMMA GEMM, 3 products, LDSM fragment loads ----
    int e0 = w * 32;
    int q  = lane >> 2;          // fragment row group
    int kq = (lane & 3) * 2;     // fragment col pair

    float acc[2][8][4];
    #pragma unroll
    for (int mt = 0; mt < 2; mt++)
        #pragma unroll
        for (int nt = 0; nt < 8; nt++)
            #pragma unroll
            for (int t = 0; t < 4; t++) acc[mt][nt][t] = 0.f;

    uint32_t Ah32 = smem_u32(smem + A_BASE);
    uint32_t Am32 = Ah32 + 16384;
    uint32_t Bh32 = smem_u32(smem + B_BASE);
    uint32_t Bm32 = Bh32 + 8192;

    // per-lane ldmatrix row addressing
    int sub = lane >> 3, l8 = lane & 7;
    int rA[2], rA7[2];
    #pragma unroll
    for (int mt = 0; mt < 2; mt++) {
        int r = e0 + mt*16 + ((sub & 1) << 3) + l8;
        rA[mt] = r * 128;
        rA7[mt] = r & 7;
    }
    int kbitA = sub >> 1;
    int rB[4], rB7[4];
    #pragma unroll
    for (int p = 0; p < 4; p++) {
        int j = p*16 + ((sub >> 1) << 3) + l8;
        rB[p] = j * 128;
        rB7[p] = j & 7;
    }
    int kbitB = sub & 1;

    #pragma unroll
    for (int ks = 0; ks < 4; ks++) {
        uint32_t ah[2][4], am[2][4];
        #pragma unroll
        for (int mt = 0; mt < 2; mt++) {
            uint32_t off = rA[mt] + (((2*ks + kbitA) ^ rA7[mt]) << 4);
            ldsm_x4(ah[mt], Ah32 + off);
            ldsm_x4(am[mt], Am32 + off);
        }
        uint32_t bh[8][2], bm[8][2];
        #pragma unroll
        for (int p = 0; p < 4; p++) {
            uint32_t off = rB[p] + (((2*ks + kbitB) ^ rB7[p]) << 4);
            uint32_t t4[4];
            ldsm_x4(t4, Bh32 + off);
            bh[2*p][0] = t4[0]; bh[2*p][1] = t4[1];
            bh[2*p+1][0] = t4[2]; bh[2*p+1][1] = t4[3];
            ldsm_x4(t4, Bm32 + off);
            bm[2*p][0] = t4[0]; bm[2*p][1] = t4[1];
            bm[2*p+1][0] = t4[2]; bm[2*p+1][1] = t4[3];
        }
        #pragma unroll
        for (int nt = 0; nt < 8; nt++) {
            mma16816(acc[0][nt], ah[0], bh[nt][0], bh[nt][1]);   // h*h
            mma16816(acc[1][nt], ah[1], bh[nt][0], bh[nt][1]);
            mma16816(acc[0][nt], ah[0], bm[nt][0], bm[nt][1]);   // h*m
            mma16816(acc[1][nt], ah[1], bm[nt][0], bm[nt][1]);
            mma16816(acc[0][nt], am[0], bh[nt][0], bh[nt][1]);   // m*h
            mma16816(acc[1][nt], am[1], bh[nt][0], bh[nt][1]);
        }
    }

    // ---- epilogue: relu + LN2 via quad reductions -> logits ----
    {
        float2 pb2[8], pg2[8], pbe2[8], pw3[8];
        #pragma unroll
        for (int nt = 0; nt < 8; nt++) {
            int jc = nt*8 + kq;
            pb2[nt]  = *(const float2*)&sp_b2[jc];
            pg2[nt]  = *(const float2*)&sp_g2[jc];
            pbe2[nt] = *(const float2*)&sp_be2[jc];
            pw3[nt]  = *(const float2*)&sp_w3[jc];
        }
        float b3v = __ldg(&b3[0]);
        float* lrow = g_logits + (b*TT + i)*NSRC;

        #pragma unroll
        for (int mt = 0; mt < 2; mt++) {
            float xA[16], xB[16];
            float sA = 0.f, sB = 0.f;
            #pragma unroll
            for (int nt = 0; nt < 8; nt++) {
                xA[2*nt]   = fmaxf(acc[mt][nt][0] + pb2[nt].x, 0.f);
                xA[2*nt+1] = fmaxf(acc[mt][nt][1] + pb2[nt].y, 0.f);
                xB[2*nt]   = fmaxf(acc[mt][nt][2] + pb2[nt].x, 0.f);
                xB[2*nt+1] = fmaxf(acc[mt][nt][3] + pb2[nt].y, 0.f);
                sA += xA[2*nt] + xA[2*nt+1];
                sB += xB[2*nt] + xB[2*nt+1];
            }
            sA += __shfl_xor_sync(0xffffffffu, sA, 1);
            sA += __shfl_xor_sync(0xffffffffu, sA, 2);
            sB += __shfl_xor_sync(0xffffffffu, sB, 1);
            sB += __shfl_xor_sync(0xffffffffu, sB, 2);
            float muA = sA * (1.f/64.f), muB = sB * (1.f/64.f);
            float vA = 0.f, vB = 0.f;
            #pragma unroll
            for (int t = 0; t < 16; t++) {
                float dA = xA[t] - muA; vA += dA*dA;
                float dB = xB[t] - muB; vB += dB*dB;
            }
            vA += __shfl_xor_sync(0xffffffffu, vA, 1);
            vA += __shfl_xor_sync(0xffffffffu, vA, 2);
            vB += __shfl_xor_sync(0xffffffffu, vB, 1);
            vB += __shfl_xor_sync(0xffffffffu, vB, 2);
            float rsA = 1.f / sqrtf(vA * (1.f/64.f) + 1e-5f);
            float rsB = 1.f / sqrtf(vB * (1.f/64.f) + 1e-5f);
            float dA = 0.f, dB = 0.f;
            #pragma unroll
            for (int nt = 0; nt < 8; nt++) {
                dA = fmaf(fmaf((xA[2*nt]   - muA)*rsA, pg2[nt].x, pbe2[nt].x), pw3[nt].x, dA);
                dA = fmaf(fmaf((xA[2*nt+1] - muA)*rsA, pg2[nt].y, pbe2[nt].y), pw3[nt].y, dA);
                dB = fmaf(fmaf((xB[2*nt]   - muB)*rsB, pg2[nt].x, pbe2[nt].x), pw3[nt].x, dB);
                dB = fmaf(fmaf((xB[2*nt+1] - muB)*rsB, pg2[nt].y, pbe2[nt].y), pw3[nt].y, dB);
            }
            dA += __shfl_xor_sync(0xffffffffu, dA, 1);
            dA += __shfl_xor_sync(0xffffffffu, dA, 2);
            dB += __shfl_xor_sync(0xffffffffu, dB, 1);
            dB += __shfl_xor_sync(0xffffffffu, dB, 2);
            if ((lane & 3) == 0) {
                int eA = e0 + mt*16 + q;
                int cA = c_base + eA;
                if (cA < L) lrow[cA] = dA + b3v;
                int cB = cA + 8;
                if (cB < L) lrow[cB] = dB + b3v;
            }
        }
    }
}

// ---------------- K4: gumbel argmax + scatter 1.0 ----------------
__global__ void k_argmax(const float* __restrict__ gumbel, float* __restrict__ out)
{
    int row = blockIdx.x * 8 + (threadIdx.x >> 5);
    if (row >= NROWS) return;
    int lane = threadIdx.x & 31;
    int i  = row % TT;
    int sb = row / TT;
    int b  = sb & 7;
    int L  = 192 + i;

    const float* lg = g_logits + (size_t)((b*TT + i)) * NSRC;
    const float* gb = gumbel   + (size_t)row * NSRC;

    float best = -__int_as_float(0x7f800000);
    int bidx = 0;
    int c = lane;
    for (; c + 96 < L; c += 128) {           // 4-way unroll for MLP
        float v0 = __ldg(&lg[c])      + __ldg(&gb[c]);
        float v1 = __ldg(&lg[c + 32]) + __ldg(&gb[c + 32]);
        float v2 = __ldg(&lg[c + 64]) + __ldg(&gb[c + 64]);
        float v3 = __ldg(&lg[c + 96]) + __ldg(&gb[c + 96]);
        if (v0 > best) { best = v0; bidx = c; }
        if (v1 > best) { best = v1; bidx = c + 32; }
        if (v2 > best) { best = v2; bidx = c + 64; }
        if (v3 > best) { best = v3; bidx = c + 96; }
    }
    for (; c < L; c += 32) {
        float v = __ldg(&lg[c]) + __ldg(&gb[c]);
        if (v > best) { best = v; bidx = c; }
    }
    #pragma unroll
    for (int o = 16; o; o >>= 1) {
        float ov = __shfl_xor_sync(0xffffffffu, best, o);
        int   oi = __shfl_xor_sync(0xffffffffu, bidx, o);
        if (ov > best || (ov == best && oi < bidx)) { best = ov; bidx = oi; }
    }
    if (lane == 0)
        out[((size_t)(b*NNODE) + 192 + i) * NNODE + bidx] = 1.0f;
}

// ---------------- launch ----------------
extern "C" void kernel_launch(void* const* d_in, const int* in_sizes, int n_in,
                              void* d_out, int out_size)
{
    const float* nodes = (const float*)d_in[0];
    const float* w1    = (const float*)d_in[1];
    const float* b1    = (const float*)d_in[2];
    const float* g1    = (const float*)d_in[3];
    const float* be1   = (const float*)d_in[4];
    const float* w2    = (const float*)d_in[5];
    const float* b2    = (const float*)d_in[6];
    const float* g2    = (const float*)d_in[7];
    const float* be2   = (const float*)d_in[8];
    const float* w3    = (const float*)d_in[9];
    const float* b3    = (const float*)d_in[10];
    const float* gum   = (const float*)d_in[11];
    float* out = (float*)d_out;

    cudaFuncSetAttribute(k_edges, cudaFuncAttributeMaxDynamicSharedMemorySize,
                         SMEM_BYTES);

    k_precompute<<<384, 256>>>(nodes, w1, b1, w2);
    k_edges<<<dim3(3, TT, BB), 128, SMEM_BYTES>>>(b2, g2, be2, w3, b3, g1, be1,
                                                  (float4*)out);
    k_argmax<<<NROWS / 8, 256>>>(gum, out);
}